// round 16
// baseline (speedup 1.0000x reference)
#include <cuda_runtime.h>
#include <cuda_fp16.h>

// ---------------------------------------------------------------------------
// GAT layer: CSR-gather + fp16 tensor-core GEMM (hi/lo split, m16n8k16).
// All GEMM inputs pre-split ONCE into global fp16 {hi,lo} pairs (4B/elem =
// same bytes as fp32): x_hl, W_hl (x16 scaled), and aggregate writes agg as
// hl pairs. GEMM hot loop = pure LDS.64 + mma, zero cvt. K/V stored fp16.
// Two-stream overlap: CSR build on s2 under split+QKV on main.
// ---------------------------------------------------------------------------

#define MAXN 50048
#define MAXE 1600000
#define SCAN_BLK 1024
#define MAX_SBLKS 64

__device__ float  g_Q[MAXN * 128];
__device__ __half g_Kh[MAXN * 128];
__device__ __half g_Vh[MAXN * 128];
__device__ uint2  g_agghl[MAXN * 64];   // agg as fp16 {hi2,lo2} per k-pair
__device__ uint2  g_xhl[MAXN * 64];     // x  as fp16 {hi2,lo2} per k-pair
__device__ uint2  g_Whl[4 * 128 * 64];  // Wq,Wk,Wv,Wo (x16 scaled)
__device__ int    g_off[MAXN + 1];
__device__ int    g_cur[MAXN];
__device__ int    g_srcs[MAXE];
__device__ int    g_bsum[MAX_SBLKS];
__device__ int    g_idx64;

__device__ __forceinline__ int load_idx(const void* ei, long long pos, int M) {
    int v;
    if (g_idx64) v = (int)((const long long*)ei)[pos];
    else         v = ((const int*)ei)[pos];
    v = v < 0 ? 0 : (v >= M ? M - 1 : v);
    return v;
}

__device__ __forceinline__ uint2 h2_split2(float x, float y) {
    __half hx = __float2half_rn(x);
    __half hy = __float2half_rn(y);
    __half lx = __float2half_rn(x - __half2float(hx));
    __half ly = __float2half_rn(y - __half2float(hy));
    __half2 h = __halves2half2(hx, hy);
    __half2 l = __halves2half2(lx, ly);
    uint2 r;
    r.x = *(unsigned*)&h;
    r.y = *(unsigned*)&l;
    return r;
}

// ---------------------------------------------------------------------------
// Pre-split x and the 4 weight matrices into fp16 hi/lo pair form.
// ---------------------------------------------------------------------------
__global__ void split_kernel(const float* __restrict__ x,
                             const float* __restrict__ Wq,
                             const float* __restrict__ Wk,
                             const float* __restrict__ Wv,
                             const float* __restrict__ Wo,
                             int M)
{
    int xp = M * 64;                       // x pairs
    int t = blockIdx.x * blockDim.x + threadIdx.x;
    if (t < xp) {
        g_xhl[t] = h2_split2(x[2 * t], x[2 * t + 1]);
        return;
    }
    int r = t - xp;                        // W pair index: 4 * 8192
    if (r >= 4 * 8192) return;
    int mat = r >> 13;                     // 0..3
    int p   = r & 8191;
    const float* W = (mat == 0) ? Wq : (mat == 1) ? Wk : (mat == 2) ? Wv : Wo;
    g_Whl[mat * 8192 + p] = h2_split2(W[2 * p] * 16.f, W[2 * p + 1] * 16.f);
}

// ---------------------------------------------------------------------------
__global__ void zero_detect(const unsigned* __restrict__ ei_u32, int M) {
    int t = blockIdx.x * blockDim.x + threadIdx.x;
    if (t < M) g_off[t] = 0;
    if (t == 0) {
        int is64 = 1;
        for (int i = 0; i < 128; i++)
            if (ei_u32[2 * i + 1] != 0u) { is64 = 0; break; }
        g_idx64 = is64;
    }
}

__global__ void hist_kernel(const void* __restrict__ ei, int E, int M) {
    int t = blockIdx.x * blockDim.x + threadIdx.x;
    if (t >= E) return;
    int dst = load_idx(ei, (long long)E + t, M);
    atomicAdd(&g_off[dst], 1);
}

__global__ void scan_partial(int M) {
    __shared__ int wsum[32];
    int tid  = threadIdx.x;
    int gi   = blockIdx.x * SCAN_BLK + tid;
    int lane = tid & 31;
    int wid  = tid >> 5;

    int v = (gi < M) ? g_off[gi] : 0;

    int x = v;
#pragma unroll
    for (int o = 1; o < 32; o <<= 1) {
        int y = __shfl_up_sync(0xFFFFFFFFu, x, o);
        if (lane >= o) x += y;
    }
    if (lane == 31) wsum[wid] = x;
    __syncthreads();

    if (wid == 0) {
        int w = wsum[lane];
#pragma unroll
        for (int o = 1; o < 32; o <<= 1) {
            int y = __shfl_up_sync(0xFFFFFFFFu, w, o);
            if (lane >= o) w += y;
        }
        wsum[lane] = w;
    }
    __syncthreads();

    int incl = x + (wid > 0 ? wsum[wid - 1] : 0);
    int excl = incl - v;
    if (gi < M) g_off[gi] = excl;
    if (tid == SCAN_BLK - 1) g_bsum[blockIdx.x] = incl;
}

__global__ void scan_bsums(int nb) {
    __shared__ int s[MAX_SBLKS];
    int lane = threadIdx.x;
    if (lane < MAX_SBLKS) s[lane] = (lane < nb) ? g_bsum[lane] : 0;
    __syncthreads();
    if (lane == 0) {
        int run = 0;
        for (int i = 0; i < nb; i++) { int t = s[i]; s[i] = run; run += t; }
        s[nb] = run;
    }
    __syncthreads();
    if (lane <= nb) g_bsum[lane] = s[lane];
}

__global__ void scan_add(int M) {
    int tid = threadIdx.x;
    int gi  = blockIdx.x * SCAN_BLK + tid;
    if (gi < M) {
        int o = g_off[gi] + g_bsum[blockIdx.x];
        g_off[gi] = o;
        g_cur[gi] = o;
    }
    if (gi == M) {
        int nb = (M + SCAN_BLK - 1) / SCAN_BLK;
        g_off[M] = g_bsum[nb];
    }
}

__global__ void scatter_kernel(const void* __restrict__ ei, int E, int M) {
    int t = blockIdx.x * blockDim.x + threadIdx.x;
    if (t >= E) return;
    int src = load_idx(ei, t, M);
    int dst = load_idx(ei, (long long)E + t, M);
    int pos = atomicAdd(&g_cur[dst], 1);
    g_srcs[pos] = src;
}

// ---------------------------------------------------------------------------
// fp16 tensor-core GEMM over pre-split hi/lo inputs.
//   C tile = A[128 rows, 128k] @ Whalf[64, 128]^T (+bias, +relu, x1/16)
// A, W in uint2 {hi2,lo2}-per-k-pair form. smem strides (uint2): As 20, Ws 68
// -> both ~4 mod 16 -> conflict-free LDS.64 fragment loads.
// blockIdx.y: bit0 = n-half, bits>=1 = matrix. fp16_mask -> fp16 C output.
// ---------------------------------------------------------------------------
#define WS_U2 68     // uint2 stride of Ws row (64 pairs + pad)
#define AS_U2 20     // uint2 stride of As row (16 pairs + pad)
#define GEMM_SMEM ((64 * WS_U2 + 128 * AS_U2) * 8)

__device__ __forceinline__ void mma_f16(float* d,
                                        unsigned a0, unsigned a1,
                                        unsigned a2, unsigned a3,
                                        unsigned b0, unsigned b1) {
    asm("mma.sync.aligned.m16n8k16.row.col.f32.f16.f16.f32 "
        "{%0,%1,%2,%3}, {%4,%5,%6,%7}, {%8,%9}, {%0,%1,%2,%3};"
        : "+f"(d[0]), "+f"(d[1]), "+f"(d[2]), "+f"(d[3])
        : "r"(a0), "r"(a1), "r"(a2), "r"(a3), "r"(b0), "r"(b1));
}

__global__ __launch_bounds__(256, 2)
void gemm_f16_kernel(const uint2* __restrict__ Ahl, int M,
                     const uint2* __restrict__ Whl_base, int mat_base,
                     const float* __restrict__ ba, const float* __restrict__ bb,
                     const float* __restrict__ bc,
                     void* __restrict__ Ca, void* __restrict__ Cb,
                     void* __restrict__ Cc,
                     int fp16_mask, int relu)
{
    extern __shared__ uint2 smem_u2[];
    uint2* Ws = smem_u2;                 // [64][WS_U2]
    uint2* As = smem_u2 + 64 * WS_U2;    // [128][AS_U2]

    int mat  = blockIdx.y >> 1;
    int n0   = (blockIdx.y & 1) * 64;

    const uint2* Whl = Whl_base + (size_t)(mat_base + mat) * 8192;
    const float* bias;
    void*        C;
    if (mat == 0)      { bias = ba; C = Ca; }
    else if (mat == 1) { bias = bb; C = Cb; }
    else               { bias = bc; C = Cc; }
    int h16out = (fp16_mask >> mat) & 1;

    int tid  = threadIdx.x;
    int wid  = tid >> 5;
    int lane = tid & 31;
    int g    = lane >> 2;
    int c    = lane & 3;
    int m0   = blockIdx.x * 128;

    // stage W half: 64 rows x 32 uint4 (64 pairs) = 2048 uint4, 8/thread
#pragma unroll
    for (int i = 0; i < 8; i++) {
        int idx = tid + i * 256;        // uint4 slot 0..2047
        int row = idx >> 5;             // 0..63
        int q   = idx & 31;             // uint4 within row
        uint4 w = *(const uint4*)(Whl + (size_t)(n0 + row) * 64 + 2 * q);
        *(uint4*)(Ws + row * WS_U2 + 2 * q) = w;
    }

    float acc[8][4];
#pragma unroll
    for (int t = 0; t < 8; t++)
#pragma unroll
        for (int j = 0; j < 4; j++) acc[t][j] = 0.f;

    int r0 = wid * 16 + g;

    for (int slab = 0; slab < 4; slab++) {
        __syncthreads();
        // stage A slab: 128 rows x 8 uint4 (16 pairs) = 1024 uint4, 4/thread
#pragma unroll
        for (int i = 0; i < 4; i++) {
            int idx = tid + i * 256;    // uint4 slot 0..1023
            int row = idx >> 3;         // 0..127
            int q   = idx & 7;          // uint4 within row
            uint4 v = make_uint4(0u, 0u, 0u, 0u);
            int m = m0 + row;
            if (m < M)
                v = *(const uint4*)(Ahl + (size_t)m * 64 + slab * 16 + 2 * q);
            *(uint4*)(As + row * AS_U2 + 2 * q) = v;
        }
        __syncthreads();

#pragma unroll
        for (int kk = 0; kk < 2; kk++) {
            int pa = kk * 8 + c;        // A pair index within slab
            uint2 A0 = As[r0 * AS_U2 + pa];
            uint2 A1 = As[(r0 + 8) * AS_U2 + pa];
            uint2 A2 = As[r0 * AS_U2 + pa + 4];
            uint2 A3 = As[(r0 + 8) * AS_U2 + pa + 4];

            int pb = slab * 16 + kk * 8 + c;   // W pair index (full row)
#pragma unroll
            for (int nt = 0; nt < 8; nt++) {
                int n = nt * 8 + g;
                uint2 B0 = Ws[n * WS_U2 + pb];
                uint2 B1 = Ws[n * WS_U2 + pb + 4];

                mma_f16(acc[nt], A0.x, A1.x, A2.x, A3.x, B0.y, B1.y);  // hi*lo
                mma_f16(acc[nt], A0.y, A1.y, A2.y, A3.y, B0.x, B1.x);  // lo*hi
                mma_f16(acc[nt], A0.x, A1.x, A2.x, A3.x, B0.x, B1.x);  // hi*hi
            }
        }
    }

    int mA = m0 + r0;
    int mB = mA + 8;
#pragma unroll
    for (int nt = 0; nt < 8; nt++) {
        int n = n0 + nt * 8 + 2 * c;
        float bx = bias[n], by = bias[n + 1];
        float2 oA = make_float2(fmaf(acc[nt][0], 0.0625f, bx),
                                fmaf(acc[nt][1], 0.0625f, by));
        float2 oB = make_float2(fmaf(acc[nt][2], 0.0625f, bx),
                                fmaf(acc[nt][3], 0.0625f, by));
        if (relu) {
            oA.x = fmaxf(oA.x, 0.f); oA.y = fmaxf(oA.y, 0.f);
            oB.x = fmaxf(oB.x, 0.f); oB.y = fmaxf(oB.y, 0.f);
        }
        if (h16out) {
            __half* Ch = (__half*)C;
            if (mA < M) *(__half2*)(Ch + (size_t)mA * 128 + n) =
                __floats2half2_rn(oA.x, oA.y);
            if (mB < M) *(__half2*)(Ch + (size_t)mB * 128 + n) =
                __floats2half2_rn(oB.x, oB.y);
        } else {
            float* Cf = (float*)C;
            if (mA < M) *(float2*)(Cf + (size_t)mA * 128 + n) = oA;
            if (mB < M) *(float2*)(Cf + (size_t)mB * 128 + n) = oB;
        }
    }
}

// ---------------------------------------------------------------------------
// Aggregate: two nodes per warp (16 lanes each, lane owns 8 elements).
// Output written as fp16 hi/lo pairs into g_agghl (exact to 2^-22).
// ---------------------------------------------------------------------------
__device__ __forceinline__ float dot8(const float* q, const uint4& u) {
    float2 f0 = __half22float2(*(__half2*)&u.x);
    float2 f1 = __half22float2(*(__half2*)&u.y);
    float2 f2 = __half22float2(*(__half2*)&u.z);
    float2 f3 = __half22float2(*(__half2*)&u.w);
    float r = q[0] * f0.x + q[1] * f0.y;
    r = fmaf(q[2], f1.x, r); r = fmaf(q[3], f1.y, r);
    r = fmaf(q[4], f2.x, r); r = fmaf(q[5], f2.y, r);
    r = fmaf(q[6], f3.x, r); r = fmaf(q[7], f3.y, r);
    return r;
}
__device__ __forceinline__ void acc8(float* acc, const uint4& u, float p) {
    float2 f0 = __half22float2(*(__half2*)&u.x);
    float2 f1 = __half22float2(*(__half2*)&u.y);
    float2 f2 = __half22float2(*(__half2*)&u.z);
    float2 f3 = __half22float2(*(__half2*)&u.w);
    acc[0] = fmaf(p, f0.x, acc[0]); acc[1] = fmaf(p, f0.y, acc[1]);
    acc[2] = fmaf(p, f1.x, acc[2]); acc[3] = fmaf(p, f1.y, acc[3]);
    acc[4] = fmaf(p, f2.x, acc[4]); acc[5] = fmaf(p, f2.y, acc[5]);
    acc[6] = fmaf(p, f3.x, acc[6]); acc[7] = fmaf(p, f3.y, acc[7]);
}

__global__ __launch_bounds__(256)
void aggregate_kernel(int M)
{
    long long gwarp = ((long long)blockIdx.x * blockDim.x + threadIdx.x) >> 5;
    int lane = threadIdx.x & 31;
    int slot = lane >> 4;
    int l    = lane & 15;

    long long w = gwarp * 2 + slot;
    bool valid = (w < M);
    int wi = valid ? (int)w : 0;

    int start = valid ? g_off[wi] : 0;
    int end   = valid ? g_cur[wi] : 0;
    int deg   = end - start;

    int maxdeg = deg;
    maxdeg = max(maxdeg, __shfl_xor_sync(0xFFFFFFFFu, maxdeg, 16));

    float q[8];
    {
        const float4* qp = (const float4*)(g_Q + (size_t)wi * 128 + 8 * l);
        float4 q0 = qp[0], q1 = qp[1];
        q[0] = q0.x; q[1] = q0.y; q[2] = q0.z; q[3] = q0.w;
        q[4] = q1.x; q[5] = q1.y; q[6] = q1.z; q[7] = q1.w;
    }

    float acc[8];
#pragma unroll
    for (int j = 0; j < 8; j++) acc[j] = 0.f;
    float ssum = 0.f;

    for (int t = 0; t < maxdeg; t++) {
        bool active = t < deg;
        int src = 0;
        if (active) src = g_srcs[start + t];

        uint4 k = *(const uint4*)(g_Kh + (size_t)src * 128 + 8 * l);
        uint4 v = *(const uint4*)(g_Vh + (size_t)src * 128 + 8 * l);

        float part = dot8(q, k);
        part += __shfl_xor_sync(0xFFFFFFFFu, part, 1);
        part += __shfl_xor_sync(0xFFFFFFFFu, part, 2);
        float p = active ? __expf(part * 0.17677669529663687f) : 0.f;

        acc8(acc, v, p);
        ssum += p;
    }

    if (!valid) return;
    float inv = 1.f / (ssum + 1e-8f);
    // lane owns pairs [4l, 4l+4) of this node's agg row
    uint2 o0 = h2_split2(acc[0] * inv, acc[1] * inv);
    uint2 o1 = h2_split2(acc[2] * inv, acc[3] * inv);
    uint2 o2 = h2_split2(acc[4] * inv, acc[5] * inv);
    uint2 o3 = h2_split2(acc[6] * inv, acc[7] * inv);
    uint4* op = (uint4*)(g_agghl + (size_t)wi * 64 + 4 * l);
    op[0] = make_uint4(o0.x, o0.y, o1.x, o1.y);
    op[1] = make_uint4(o2.x, o2.y, o3.x, o3.y);
}

// ---------------------------------------------------------------------------
extern "C" void kernel_launch(void* const* d_in, const int* in_sizes, int n_in,
                              void* d_out, int out_size)
{
    const float* x  = (const float*)d_in[0];
    const void*  ei = d_in[1];
    const float* Wq = (const float*)d_in[2];
    const float* bq = (const float*)d_in[3];
    const float* Wk = (const float*)d_in[4];
    const float* bk = (const float*)d_in[5];
    const float* Wv = (const float*)d_in[6];
    const float* bv = (const float*)d_in[7];
    const float* Wo = (const float*)d_in[8];
    const float* bo = (const float*)d_in[9];
    float*       out = (float*)d_out;

    int M = in_sizes[0] / 128;   // nodes
    int E = in_sizes[1] / 2;     // edges

    float *pQ;
    __half *pKh, *pVh;
    uint2 *pXhl, *pWhl, *pAgghl;
    cudaGetSymbolAddress((void**)&pQ,     g_Q);
    cudaGetSymbolAddress((void**)&pKh,    g_Kh);
    cudaGetSymbolAddress((void**)&pVh,    g_Vh);
    cudaGetSymbolAddress((void**)&pXhl,   g_xhl);
    cudaGetSymbolAddress((void**)&pWhl,   g_Whl);
    cudaGetSymbolAddress((void**)&pAgghl, g_agghl);

    cudaFuncSetAttribute(gemm_f16_kernel,
                         cudaFuncAttributeMaxDynamicSharedMemorySize, GEMM_SMEM);

    static cudaStream_t s2 = 0;
    static cudaEvent_t  evFork = 0, evJoin = 0;
    if (!s2) {
        cudaStreamCreateWithFlags(&s2, cudaStreamNonBlocking);
        cudaEventCreateWithFlags(&evFork, cudaEventDisableTiming);
        cudaEventCreateWithFlags(&evJoin, cudaEventDisableTiming);
    }

    int nb = (M + SCAN_BLK - 1) / SCAN_BLK;   // 49 for M=50000

    cudaEventRecord(evFork, 0);
    cudaStreamWaitEvent(s2, evFork, 0);

    zero_detect<<<(M + 255) / 256, 256, 0, s2>>>((const unsigned*)ei, M);
    hist_kernel<<<(E + 255) / 256, 256, 0, s2>>>(ei, E, M);
    scan_partial<<<nb, SCAN_BLK, 0, s2>>>(M);
    scan_bsums<<<1, MAX_SBLKS, 0, s2>>>(nb);
    scan_add<<<nb + 1, SCAN_BLK, 0, s2>>>(M);
    scatter_kernel<<<(E + 255) / 256, 256, 0, s2>>>(ei, E, M);
    cudaEventRecord(evJoin, s2);

    // pre-split x + all W's, then QKV GEMM (main stream)
    int total_pairs = M * 64 + 4 * 8192;
    split_kernel<<<(total_pairs + 255) / 256, 256>>>(x, Wq, Wk, Wv, Wo, M);

    dim3 gqkv((M + 127) / 128, 6);   // 3 matrices x 2 n-halves
    gemm_f16_kernel<<<gqkv, 256, GEMM_SMEM>>>(pXhl, M, pWhl, /*mat_base=*/0,
                                              bq, bk, bv,
                                              pQ, pKh, pVh,
                                              /*fp16_mask=*/0b110, 0);

    cudaStreamWaitEvent(0, evJoin, 0);

    long long warps = (M + 1) / 2;
    long long threads = warps * 32;
    aggregate_kernel<<<(int)((threads + 255) / 256), 256>>>(M);

    dim3 gout((M + 127) / 128, 2);   // 1 matrix x 2 n-halves
    gemm_f16_kernel<<<gout, 256, GEMM_SMEM>>>(pAgghl, M, pWhl, /*mat_base=*/3,
                                              bo, bo, bo,
                                              out, out, out,
                                              /*fp16_mask=*/0, 1);
}

// round 17
// speedup vs baseline: 1.1042x; 1.1042x over previous
#include <cuda_runtime.h>
#include <cuda_fp16.h>

// ---------------------------------------------------------------------------
// GAT layer: CSR-gather + fp16 tensor-core GEMM (hi/lo split, m16n8k16),
// K/V stored fp16, two-stream overlap.
// Aggregate: TWO nodes per warp (16 lanes each, lane owns 8 elements).
// R17: R15 structure, GEMM occupancy raised to 3 CTAs/SM.
// ---------------------------------------------------------------------------

#define MAXN 50048
#define MAXE 1600000
#define SCAN_BLK 1024
#define MAX_SBLKS 64

__device__ float  g_Q[MAXN * 128];
__device__ __half g_Kh[MAXN * 128];
__device__ __half g_Vh[MAXN * 128];
__device__ float  g_agg[MAXN * 128];
__device__ int    g_off[MAXN + 1];   // CSR row starts
__device__ int    g_cur[MAXN];       // scatter cursors; == row end after sort
__device__ int    g_srcs[MAXE];      // src ids sorted by dst
__device__ int    g_bsum[MAX_SBLKS]; // per-block sums for scan
__device__ int    g_idx64;           // 1 if edge_index is int64, 0 if int32

__device__ __forceinline__ int load_idx(const void* ei, long long pos, int M) {
    int v;
    if (g_idx64) v = (int)((const long long*)ei)[pos];
    else         v = ((const int*)ei)[pos];
    v = v < 0 ? 0 : (v >= M ? M - 1 : v);   // defensive clamp
    return v;
}

// ---------------------------------------------------------------------------
__global__ void zero_detect(const unsigned* __restrict__ ei_u32, int M) {
    int t = blockIdx.x * blockDim.x + threadIdx.x;
    if (t < M) g_off[t] = 0;          // reuse g_off as degree counter
    if (t == 0) {
        int is64 = 1;
        for (int i = 0; i < 128; i++)
            if (ei_u32[2 * i + 1] != 0u) { is64 = 0; break; }
        g_idx64 = is64;
    }
}

__global__ void hist_kernel(const void* __restrict__ ei, int E, int M) {
    int t = blockIdx.x * blockDim.x + threadIdx.x;
    if (t >= E) return;
    int dst = load_idx(ei, (long long)E + t, M);
    atomicAdd(&g_off[dst], 1);
}

// ---------------------------------------------------------------------------
__global__ void scan_partial(int M) {
    __shared__ int wsum[32];
    int tid  = threadIdx.x;
    int gi   = blockIdx.x * SCAN_BLK + tid;
    int lane = tid & 31;
    int wid  = tid >> 5;

    int v = (gi < M) ? g_off[gi] : 0;

    int x = v;
#pragma unroll
    for (int o = 1; o < 32; o <<= 1) {
        int y = __shfl_up_sync(0xFFFFFFFFu, x, o);
        if (lane >= o) x += y;
    }
    if (lane == 31) wsum[wid] = x;
    __syncthreads();

    if (wid == 0) {
        int w = wsum[lane];
#pragma unroll
        for (int o = 1; o < 32; o <<= 1) {
            int y = __shfl_up_sync(0xFFFFFFFFu, w, o);
            if (lane >= o) w += y;
        }
        wsum[lane] = w;
    }
    __syncthreads();

    int incl = x + (wid > 0 ? wsum[wid - 1] : 0);
    int excl = incl - v;
    if (gi < M) g_off[gi] = excl;
    if (tid == SCAN_BLK - 1) g_bsum[blockIdx.x] = incl;
}

__global__ void scan_bsums(int nb) {
    __shared__ int s[MAX_SBLKS];
    int lane = threadIdx.x;
    if (lane < MAX_SBLKS) s[lane] = (lane < nb) ? g_bsum[lane] : 0;
    __syncthreads();
    if (lane == 0) {
        int run = 0;
        for (int i = 0; i < nb; i++) { int t = s[i]; s[i] = run; run += t; }
        s[nb] = run;
    }
    __syncthreads();
    if (lane <= nb) g_bsum[lane] = s[lane];
}

__global__ void scan_add(int M) {
    int tid = threadIdx.x;
    int gi  = blockIdx.x * SCAN_BLK + tid;
    if (gi < M) {
        int o = g_off[gi] + g_bsum[blockIdx.x];
        g_off[gi] = o;
        g_cur[gi] = o;
    }
    if (gi == M) {
        int nb = (M + SCAN_BLK - 1) / SCAN_BLK;
        g_off[M] = g_bsum[nb];
    }
}

__global__ void scatter_kernel(const void* __restrict__ ei, int E, int M) {
    int t = blockIdx.x * blockDim.x + threadIdx.x;
    if (t >= E) return;
    int src = load_idx(ei, t, M);
    int dst = load_idx(ei, (long long)E + t, M);
    int pos = atomicAdd(&g_cur[dst], 1);
    g_srcs[pos] = src;
}

// ---------------------------------------------------------------------------
// fp16 tensor-core GEMM, hi/lo split (~22-bit mantissa):
//   C tile = A[128 rows, 128k] @ Whalf[64, 128]^T + bias (+relu)
// W half pre-scaled x16 and converted ONCE to {hi2, lo2} uint2 per k-pair
// (stride 136 words: conflict-free LDS.64). A fp32 smem (stride 36),
// converted to fp16 hi/lo fragments in-loop. 3 mma terms, fp32 accum, x1/16.
// blockIdx.y: bit0 = n-half (0/1), bits>=1 = matrix select (QKV fusion).
// fp16_mask bit `mat` set -> C is written as fp16 instead of fp32.
// ---------------------------------------------------------------------------
#define WHL_STRIDE 136
#define AS_STRIDE 36
#define GEMM_SMEM ((64 * WHL_STRIDE + 128 * AS_STRIDE) * 4)

__device__ __forceinline__ uint2 h2_split2(float x, float y) {
    __half hx = __float2half_rn(x);
    __half hy = __float2half_rn(y);
    __half lx = __float2half_rn(x - __half2float(hx));
    __half ly = __float2half_rn(y - __half2float(hy));
    __half2 h = __halves2half2(hx, hy);
    __half2 l = __halves2half2(lx, ly);
    uint2 r;
    r.x = *(unsigned*)&h;
    r.y = *(unsigned*)&l;
    return r;
}

__device__ __forceinline__ void mma_f16(float* d,
                                        unsigned a0, unsigned a1,
                                        unsigned a2, unsigned a3,
                                        unsigned b0, unsigned b1) {
    asm("mma.sync.aligned.m16n8k16.row.col.f32.f16.f16.f32 "
        "{%0,%1,%2,%3}, {%4,%5,%6,%7}, {%8,%9}, {%0,%1,%2,%3};"
        : "+f"(d[0]), "+f"(d[1]), "+f"(d[2]), "+f"(d[3])
        : "r"(a0), "r"(a1), "r"(a2), "r"(a3), "r"(b0), "r"(b1));
}

__global__ __launch_bounds__(256, 3)
void gemm_f16_kernel(const float* __restrict__ A, int M,
                     const float* __restrict__ Wa, const float* __restrict__ Wb,
                     const float* __restrict__ Wc,
                     const float* __restrict__ ba, const float* __restrict__ bb,
                     const float* __restrict__ bc,
                     void* __restrict__ Ca, void* __restrict__ Cb,
                     void* __restrict__ Cc,
                     int fp16_mask, int relu)
{
    extern __shared__ unsigned smem_u[];
    unsigned* Ws = smem_u;                             // [64][WHL_STRIDE]
    float*    As = (float*)(smem_u + 64 * WHL_STRIDE); // [128][AS_STRIDE]

    int mat  = blockIdx.y >> 1;
    int n0   = (blockIdx.y & 1) * 64;    // n-half offset

    const float* W;
    const float* bias;
    void*        C;
    if (mat == 0)      { W = Wa; bias = ba; C = Ca; }
    else if (mat == 1) { W = Wb; bias = bb; C = Cb; }
    else               { W = Wc; bias = bc; C = Cc; }
    int h16out = (fp16_mask >> mat) & 1;

    int tid  = threadIdx.x;
    int wid  = tid >> 5;
    int lane = tid & 31;
    int g    = lane >> 2;
    int c    = lane & 3;
    int m0   = blockIdx.x * 128;

#pragma unroll
    for (int i = 0; i < 8; i++) {
        int i4  = tid + i * 256;
        int row = i4 >> 5;
        int c4  = (i4 & 31) * 4;
        float4 w = *(const float4*)(W + (size_t)(n0 + row) * 128 + c4);
        uint2* p = (uint2*)(Ws + row * WHL_STRIDE) + (c4 >> 1);
        p[0] = h2_split2(w.x * 16.f, w.y * 16.f);
        p[1] = h2_split2(w.z * 16.f, w.w * 16.f);
    }

    float acc[8][4];
#pragma unroll
    for (int t = 0; t < 8; t++)
#pragma unroll
        for (int j = 0; j < 4; j++) acc[t][j] = 0.f;

    int r0 = wid * 16 + g;

    for (int slab = 0; slab < 4; slab++) {
        __syncthreads();
#pragma unroll
        for (int i = 0; i < 4; i++) {
            int idx = tid + i * 256;
            int row = idx >> 3;
            int kq  = idx & 7;
            float4 v = make_float4(0.f, 0.f, 0.f, 0.f);
            int m = m0 + row;
            if (m < M)
                v = *(const float4*)(A + (size_t)m * 128 + slab * 32 + kq * 4);
            float* p = As + row * AS_STRIDE + kq * 4;
            p[0] = v.x; p[1] = v.y; p[2] = v.z; p[3] = v.w;
        }
        __syncthreads();

#pragma unroll
        for (int kk = 0; kk < 2; kk++) {
            int kl = kk * 16;
            uint2 A0 = h2_split2(As[r0 * AS_STRIDE + kl + 2 * c],
                                 As[r0 * AS_STRIDE + kl + 2 * c + 1]);
            uint2 A1 = h2_split2(As[(r0 + 8) * AS_STRIDE + kl + 2 * c],
                                 As[(r0 + 8) * AS_STRIDE + kl + 2 * c + 1]);
            uint2 A2 = h2_split2(As[r0 * AS_STRIDE + kl + 8 + 2 * c],
                                 As[r0 * AS_STRIDE + kl + 8 + 2 * c + 1]);
            uint2 A3 = h2_split2(As[(r0 + 8) * AS_STRIDE + kl + 8 + 2 * c],
                                 As[(r0 + 8) * AS_STRIDE + kl + 8 + 2 * c + 1]);

            int kp0 = slab * 16 + kk * 8 + c;
#pragma unroll
            for (int nt = 0; nt < 8; nt++) {
                int n = nt * 8 + g;
                uint2 B0 = *((const uint2*)(Ws + n * WHL_STRIDE) + kp0);
                uint2 B1 = *((const uint2*)(Ws + n * WHL_STRIDE) + kp0 + 4);

                mma_f16(acc[nt], A0.x, A1.x, A2.x, A3.x, B0.y, B1.y);  // hi*lo
                mma_f16(acc[nt], A0.y, A1.y, A2.y, A3.y, B0.x, B1.x);  // lo*hi
                mma_f16(acc[nt], A0.x, A1.x, A2.x, A3.x, B0.x, B1.x);  // hi*hi
            }
        }
    }

    int mA = m0 + r0;
    int mB = mA + 8;
#pragma unroll
    for (int nt = 0; nt < 8; nt++) {
        int n = n0 + nt * 8 + 2 * c;
        float bx = bias[n], by = bias[n + 1];
        float2 oA = make_float2(fmaf(acc[nt][0], 0.0625f, bx),
                                fmaf(acc[nt][1], 0.0625f, by));
        float2 oB = make_float2(fmaf(acc[nt][2], 0.0625f, bx),
                                fmaf(acc[nt][3], 0.0625f, by));
        if (relu) {
            oA.x = fmaxf(oA.x, 0.f); oA.y = fmaxf(oA.y, 0.f);
            oB.x = fmaxf(oB.x, 0.f); oB.y = fmaxf(oB.y, 0.f);
        }
        if (h16out) {
            __half* Ch = (__half*)C;
            if (mA < M) *(__half2*)(Ch + (size_t)mA * 128 + n) =
                __floats2half2_rn(oA.x, oA.y);
            if (mB < M) *(__half2*)(Ch + (size_t)mB * 128 + n) =
                __floats2half2_rn(oB.x, oB.y);
        } else {
            float* Cf = (float*)C;
            if (mA < M) *(float2*)(Cf + (size_t)mA * 128 + n) = oA;
            if (mB < M) *(float2*)(Cf + (size_t)mB * 128 + n) = oB;
        }
    }
}

// ---------------------------------------------------------------------------
// Aggregate: two nodes per warp. lane = 16*slot + l; lane owns elements
// [8l, 8l+8) (head = l>>2) of its slot's node. Per step: one edge per slot;
// K/V row loaded as uint4 per lane; head dot via shfl_xor(1,2); one MUFU;
// acc/ssum in fp32; lane writes its 8 outputs (no combine shfls).
// ---------------------------------------------------------------------------
__device__ __forceinline__ float dot8(const float* q, const uint4& u) {
    float2 f0 = __half22float2(*(__half2*)&u.x);
    float2 f1 = __half22float2(*(__half2*)&u.y);
    float2 f2 = __half22float2(*(__half2*)&u.z);
    float2 f3 = __half22float2(*(__half2*)&u.w);
    float r = q[0] * f0.x + q[1] * f0.y;
    r = fmaf(q[2], f1.x, r); r = fmaf(q[3], f1.y, r);
    r = fmaf(q[4], f2.x, r); r = fmaf(q[5], f2.y, r);
    r = fmaf(q[6], f3.x, r); r = fmaf(q[7], f3.y, r);
    return r;
}
__device__ __forceinline__ void acc8(float* acc, const uint4& u, float p) {
    float2 f0 = __half22float2(*(__half2*)&u.x);
    float2 f1 = __half22float2(*(__half2*)&u.y);
    float2 f2 = __half22float2(*(__half2*)&u.z);
    float2 f3 = __half22float2(*(__half2*)&u.w);
    acc[0] = fmaf(p, f0.x, acc[0]); acc[1] = fmaf(p, f0.y, acc[1]);
    acc[2] = fmaf(p, f1.x, acc[2]); acc[3] = fmaf(p, f1.y, acc[3]);
    acc[4] = fmaf(p, f2.x, acc[4]); acc[5] = fmaf(p, f2.y, acc[5]);
    acc[6] = fmaf(p, f3.x, acc[6]); acc[7] = fmaf(p, f3.y, acc[7]);
}

__global__ __launch_bounds__(256)
void aggregate_kernel(int M)
{
    long long gwarp = ((long long)blockIdx.x * blockDim.x + threadIdx.x) >> 5;
    int lane = threadIdx.x & 31;
    int slot = lane >> 4;       // node slot 0/1
    int l    = lane & 15;       // element chunk [8l, 8l+8)

    long long w = gwarp * 2 + slot;   // this slot's node
    bool valid = (w < M);
    int wi = valid ? (int)w : 0;

    int start = valid ? g_off[wi] : 0;
    int end   = valid ? g_cur[wi] : 0;
    int deg   = end - start;

    int maxdeg = deg;
    maxdeg = max(maxdeg, __shfl_xor_sync(0xFFFFFFFFu, maxdeg, 16));

    float q[8];
    {
        const float4* qp = (const float4*)(g_Q + (size_t)wi * 128 + 8 * l);
        float4 q0 = qp[0], q1 = qp[1];
        q[0] = q0.x; q[1] = q0.y; q[2] = q0.z; q[3] = q0.w;
        q[4] = q1.x; q[5] = q1.y; q[6] = q1.z; q[7] = q1.w;
    }

    float acc[8];
#pragma unroll
    for (int j = 0; j < 8; j++) acc[j] = 0.f;
    float ssum = 0.f;

    for (int t = 0; t < maxdeg; t++) {
        bool active = t < deg;
        int src = 0;
        if (active) src = g_srcs[start + t];   // broadcast within 16 lanes

        uint4 k = *(const uint4*)(g_Kh + (size_t)src * 128 + 8 * l);
        uint4 v = *(const uint4*)(g_Vh + (size_t)src * 128 + 8 * l);

        float part = dot8(q, k);
        part += __shfl_xor_sync(0xFFFFFFFFu, part, 1);
        part += __shfl_xor_sync(0xFFFFFFFFu, part, 2);   // 4-lane head dot
        float p = active ? __expf(part * 0.17677669529663687f) : 0.f;

        acc8(acc, v, p);
        ssum += p;
    }

    if (!valid) return;
    float inv = 1.f / (ssum + 1e-8f);
    float4 o0 = make_float4(acc[0] * inv, acc[1] * inv, acc[2] * inv, acc[3] * inv);
    float4 o1 = make_float4(acc[4] * inv, acc[5] * inv, acc[6] * inv, acc[7] * inv);
    float4* op = (float4*)(g_agg + (size_t)wi * 128 + 8 * l);
    op[0] = o0;
    op[1] = o1;
}

// ---------------------------------------------------------------------------
extern "C" void kernel_launch(void* const* d_in, const int* in_sizes, int n_in,
                              void* d_out, int out_size)
{
    const float* x  = (const float*)d_in[0];
    const void*  ei = d_in[1];
    const float* Wq = (const float*)d_in[2];
    const float* bq = (const float*)d_in[3];
    const float* Wk = (const float*)d_in[4];
    const float* bk = (const float*)d_in[5];
    const float* Wv = (const float*)d_in[6];
    const float* bv = (const float*)d_in[7];
    const float* Wo = (const float*)d_in[8];
    const float* bo = (const float*)d_in[9];
    float*       out = (float*)d_out;

    int M = in_sizes[0] / 128;   // nodes
    int E = in_sizes[1] / 2;     // edges

    float *pQ, *pAgg;
    __half *pKh, *pVh;
    cudaGetSymbolAddress((void**)&pQ,   g_Q);
    cudaGetSymbolAddress((void**)&pKh,  g_Kh);
    cudaGetSymbolAddress((void**)&pVh,  g_Vh);
    cudaGetSymbolAddress((void**)&pAgg, g_agg);

    cudaFuncSetAttribute(gemm_f16_kernel,
                         cudaFuncAttributeMaxDynamicSharedMemorySize, GEMM_SMEM);

    static cudaStream_t s2 = 0;
    static cudaEvent_t  evFork = 0, evJoin = 0;
    if (!s2) {
        cudaStreamCreateWithFlags(&s2, cudaStreamNonBlocking);
        cudaEventCreateWithFlags(&evFork, cudaEventDisableTiming);
        cudaEventCreateWithFlags(&evJoin, cudaEventDisableTiming);
    }

    int nb = (M + SCAN_BLK - 1) / SCAN_BLK;   // 49 for M=50000

    cudaEventRecord(evFork, 0);
    cudaStreamWaitEvent(s2, evFork, 0);

    zero_detect<<<(M + 255) / 256, 256, 0, s2>>>((const unsigned*)ei, M);
    hist_kernel<<<(E + 255) / 256, 256, 0, s2>>>(ei, E, M);
    scan_partial<<<nb, SCAN_BLK, 0, s2>>>(M);
    scan_bsums<<<1, MAX_SBLKS, 0, s2>>>(nb);
    scan_add<<<nb + 1, SCAN_BLK, 0, s2>>>(M);
    scatter_kernel<<<(E + 255) / 256, 256, 0, s2>>>(ei, E, M);
    cudaEventRecord(evJoin, s2);

    dim3 gqkv((M + 127) / 128, 6);   // 3 matrices x 2 n-halves
    gemm_f16_kernel<<<gqkv, 256, GEMM_SMEM>>>(x, M, Wq, Wk, Wv, bq, bk, bv,
                                              pQ, pKh, pVh,
                                              /*fp16_mask=*/0b110, 0);

    cudaStreamWaitEvent(0, evJoin, 0);

    long long warps = (M + 1) / 2;
    long long threads = warps * 32;
    aggregate_kernel<<<(int)((threads + 255) / 256), 256>>>(M);

    dim3 gout((M + 127) / 128, 2);   // 1 matrix x 2 n-halves
    gemm_f16_kernel<<<gout, 256, GEMM_SMEM>>>(pAgg, M, Wo, Wo, Wo, bo, bo, bo,
                                              out, out, out,
                                              /*fp16_mask=*/0, 1);
}